// round 1
// baseline (speedup 1.0000x reference)
#include <cuda_runtime.h>

#define NN 50000
#define NE 500000
#define D 128
#define TDIM 32
#define EDIM 160

// ---- scratch (no cudaMalloc allowed) ----
__device__ float g_q[NN * D];
__device__ float g_k[NN * D];
__device__ float g_v[NN * D];
__device__ float g_agg[NN * D];
__device__ float g_sum[NN * 2];
__device__ int   g_idx64;

// Detect whether edge_index arrived as int64 or int32.
// If int32 data is misread as int64, each value combines two ~U[0,50000)
// ints -> astronomically unlikely that 16 consecutive reads land in [0,NN).
__global__ void detect_kernel(const long long* __restrict__ ei) {
    if (threadIdx.x == 0 && blockIdx.x == 0) {
        bool ok = true;
        #pragma unroll
        for (int i = 0; i < 16; i++) {
            long long v = ei[i];
            if (v < 0 || v >= NN) ok = false;
        }
        g_idx64 = ok ? 1 : 0;
    }
}

__global__ void zero_kernel() {
    int idx = blockIdx.x * blockDim.x + threadIdx.x;
    if (idx < NN * D) g_agg[idx] = 0.0f;
    if (idx < NN * 2) g_sum[idx] = 0.0f;
}

// One warp per node: q,k,v,skip = x @ W + b. Thread owns 4 consecutive cols.
__global__ __launch_bounds__(256) void proj_kernel(
    const float* __restrict__ x,
    const float* __restrict__ Wq, const float* __restrict__ bq,
    const float* __restrict__ Wk, const float* __restrict__ bk,
    const float* __restrict__ Wv, const float* __restrict__ bv,
    const float* __restrict__ Ws, const float* __restrict__ bs,
    float* __restrict__ out)
{
    __shared__ float xs[8][D];
    const int w    = threadIdx.x >> 5;
    const int lane = threadIdx.x & 31;
    const int node = blockIdx.x * 8 + w;
    if (node >= NN) return;

    #pragma unroll
    for (int i = 0; i < 4; i++)
        xs[w][lane + 32 * i] = x[node * D + lane + 32 * i];
    __syncwarp();

    float4 qa = {0,0,0,0}, ka = {0,0,0,0}, va = {0,0,0,0}, sa = {0,0,0,0};
    const float4* Wq4 = (const float4*)Wq;
    const float4* Wk4 = (const float4*)Wk;
    const float4* Wv4 = (const float4*)Wv;
    const float4* Ws4 = (const float4*)Ws;

    #pragma unroll 4
    for (int j = 0; j < D; j++) {
        const float xv = xs[w][j];
        const int   wo = j * 32 + lane;
        float4 a;
        a = __ldg(Wq4 + wo); qa.x += xv*a.x; qa.y += xv*a.y; qa.z += xv*a.z; qa.w += xv*a.w;
        a = __ldg(Wk4 + wo); ka.x += xv*a.x; ka.y += xv*a.y; ka.z += xv*a.z; ka.w += xv*a.w;
        a = __ldg(Wv4 + wo); va.x += xv*a.x; va.y += xv*a.y; va.z += xv*a.z; va.w += xv*a.w;
        a = __ldg(Ws4 + wo); sa.x += xv*a.x; sa.y += xv*a.y; sa.z += xv*a.z; sa.w += xv*a.w;
    }

    const int o = node * D + lane * 4;
    float4 b;
    b = __ldg((const float4*)bq + lane); qa.x += b.x; qa.y += b.y; qa.z += b.z; qa.w += b.w;
    b = __ldg((const float4*)bk + lane); ka.x += b.x; ka.y += b.y; ka.z += b.z; ka.w += b.w;
    b = __ldg((const float4*)bv + lane); va.x += b.x; va.y += b.y; va.z += b.z; va.w += b.w;
    b = __ldg((const float4*)bs + lane); sa.x += b.x; sa.y += b.y; sa.z += b.z; sa.w += b.w;

    *(float4*)(g_q + o) = qa;
    *(float4*)(g_k + o) = ka;
    *(float4*)(g_v + o) = va;
    *(float4*)(out + o) = sa;   // skip connection stored directly in output
}

// One warp per edge.
__global__ __launch_bounds__(256) void edge_kernel(
    const void*  __restrict__ ei_raw,
    const float* __restrict__ last_update,
    const float* __restrict__ t,
    const float* __restrict__ msg,
    const float* __restrict__ time_w,
    const float* __restrict__ time_b,
    const float* __restrict__ We)
{
    __shared__ float attr[8][EDIM];
    const int w    = threadIdx.x >> 5;
    const int lane = threadIdx.x & 31;
    const int e    = blockIdx.x * 8 + w;
    if (e >= NE) return;

    int src, dst;
    if (g_idx64) {
        const long long* p = (const long long*)ei_raw;
        src = (int)__ldg(p + e);
        dst = (int)__ldg(p + NE + e);
    } else {
        const int* p = (const int*)ei_raw;
        src = __ldg(p + e);
        dst = __ldg(p + NE + e);
    }

    // stage edge_attr = [cos(rel_t * w + b) (32) | msg (128)] into smem
    const float rel = __ldg(last_update + src) - __ldg(t + e);
    attr[w][lane] = cosf(rel * __ldg(time_w + lane) + __ldg(time_b + lane));
    *(float4*)&attr[w][TDIM + lane * 4] =
        __ldg((const float4*)(msg + (size_t)e * D) + lane);
    __syncwarp();

    // e = edge_attr @ We   (thread owns 4 consecutive output cols)
    float4 ea = {0,0,0,0};
    const float4* We4 = (const float4*)We;
    #pragma unroll 4
    for (int j = 0; j < EDIM; j++) {
        const float  a  = attr[w][j];
        const float4 wv = __ldg(We4 + j * 32 + lane);
        ea.x += a * wv.x; ea.y += a * wv.y; ea.z += a * wv.z; ea.w += a * wv.w;
    }

    const int col = lane * 4;                 // lanes 0..15 -> head 0, 16..31 -> head 1
    float4 kj = *(const float4*)(g_k + src * D + col);
    float4 qi = *(const float4*)(g_q + dst * D + col);
    float4 vj = *(const float4*)(g_v + src * D + col);
    kj.x += ea.x; kj.y += ea.y; kj.z += ea.z; kj.w += ea.w;
    vj.x += ea.x; vj.y += ea.y; vj.z += ea.z; vj.w += ea.w;

    float p = qi.x*kj.x + qi.y*kj.y + qi.z*kj.z + qi.w*kj.w;
    p += __shfl_xor_sync(0xffffffffu, p, 1);
    p += __shfl_xor_sync(0xffffffffu, p, 2);
    p += __shfl_xor_sync(0xffffffffu, p, 4);
    p += __shfl_xor_sync(0xffffffffu, p, 8);
    // softmax without max-subtraction (alpha is O(1); mathematically identical)
    const float ex = expf(p * 0.125f);        // 1/sqrt(64) = 0.125

    float* aggp = g_agg + dst * D + col;
    atomicAdd(aggp + 0, ex * vj.x);
    atomicAdd(aggp + 1, ex * vj.y);
    atomicAdd(aggp + 2, ex * vj.z);
    atomicAdd(aggp + 3, ex * vj.w);
    if ((lane & 15) == 0)
        atomicAdd(&g_sum[dst * 2 + (lane >> 4)], ex);
}

__global__ void finalize_kernel(float* __restrict__ out) {
    int idx = blockIdx.x * blockDim.x + threadIdx.x;   // one float4 per thread
    if (idx >= NN * 32) return;
    const int n = idx >> 5;
    const int h = (idx & 31) >> 4;
    const float inv = 1.0f / (g_sum[n * 2 + h] + 1e-16f);
    float4 a = ((const float4*)g_agg)[idx];
    float4 o = ((float4*)out)[idx];
    o.x += a.x * inv; o.y += a.y * inv; o.z += a.z * inv; o.w += a.w * inv;
    ((float4*)out)[idx] = o;
}

extern "C" void kernel_launch(void* const* d_in, const int* in_sizes, int n_in,
                              void* d_out, int out_size) {
    const float* x           = (const float*)d_in[0];
    const float* last_update = (const float*)d_in[1];
    const void*  ei          = d_in[2];
    const float* t           = (const float*)d_in[3];
    const float* msg         = (const float*)d_in[4];
    const float* time_w      = (const float*)d_in[5];
    const float* time_b      = (const float*)d_in[6];
    const float* Wq          = (const float*)d_in[7];
    const float* bq          = (const float*)d_in[8];
    const float* Wk          = (const float*)d_in[9];
    const float* bk          = (const float*)d_in[10];
    const float* Wv          = (const float*)d_in[11];
    const float* bv          = (const float*)d_in[12];
    const float* We          = (const float*)d_in[13];
    const float* Ws          = (const float*)d_in[14];
    const float* bs          = (const float*)d_in[15];
    float* out = (float*)d_out;

    detect_kernel<<<1, 32>>>((const long long*)ei);
    zero_kernel<<<(NN * D + 255) / 256, 256>>>();
    proj_kernel<<<(NN + 7) / 8, 256>>>(x, Wq, bq, Wk, bk, Wv, bv, Ws, bs, out);
    edge_kernel<<<(NE + 7) / 8, 256>>>(ei, last_update, t, msg, time_w, time_b, We);
    finalize_kernel<<<(NN * 32 + 255) / 256, 256>>>(out);
}

// round 2
// speedup vs baseline: 2.2737x; 2.2737x over previous
#include <cuda_runtime.h>

#define NN 50000
#define NE 500000
#define D 128
#define TDIM 32
#define EDIM 160
#define TE 64        // edges per block (edge kernel)
#define TNODE 64     // nodes per block (proj kernel)

// ---- scratch (no cudaMalloc allowed) ----
__device__ float g_q[NN * D];
__device__ float g_k[NN * D];
__device__ float g_v[NN * D];
__device__ float g_agg[NN * D];
__device__ float g_sum[NN * 2];
__device__ int   g_idx64;

// ---- f32x2 helpers (Blackwell packed fp32) ----
__device__ __forceinline__ unsigned long long dup2(float w) {
    unsigned long long d;
    asm("mov.b64 %0, {%1, %1};" : "=l"(d) : "r"(__float_as_uint(w)));
    return d;
}
__device__ __forceinline__ void fma2(unsigned long long& d,
                                     unsigned long long a, unsigned long long b) {
    asm("fma.rn.f32x2 %0, %1, %2, %0;" : "+l"(d) : "l"(a), "l"(b));
}
__device__ __forceinline__ float lo32(unsigned long long v) {
    return __uint_as_float((unsigned)(v & 0xffffffffu));
}
__device__ __forceinline__ float hi32(unsigned long long v) {
    return __uint_as_float((unsigned)(v >> 32));
}
__device__ __forceinline__ void red_v4(float* p, float a, float b, float c, float d) {
    asm volatile("red.global.add.v4.f32 [%0], {%1,%2,%3,%4};"
                 :: "l"(p), "f"(a), "f"(b), "f"(c), "f"(d) : "memory");
}
__device__ __forceinline__ void red_1(float* p, float a) {
    asm volatile("red.global.add.f32 [%0], %1;" :: "l"(p), "f"(a) : "memory");
}

// Detect int64 vs int32 edge_index (int32 misread as int64 can't land in [0,NN) 16x).
__global__ void detect_kernel(const long long* __restrict__ ei) {
    if (threadIdx.x == 0 && blockIdx.x == 0) {
        bool ok = true;
        #pragma unroll
        for (int i = 0; i < 16; i++) {
            long long v = ei[i];
            if (v < 0 || v >= NN) ok = false;
        }
        g_idx64 = ok ? 1 : 0;
    }
}

__global__ void zero_kernel() {
    int idx = blockIdx.x * blockDim.x + threadIdx.x;
    if (idx < NN * D) g_agg[idx] = 0.0f;
    if (idx < NN * 2) g_sum[idx] = 0.0f;
}

// ---- proj: q,k,v,skip = x @ W + b, tiled 64 nodes/block, thread = 8 nodes x 4 cols ----
__global__ __launch_bounds__(256) void proj_kernel(
    const float* __restrict__ x,
    const float* __restrict__ Wq, const float* __restrict__ bq,
    const float* __restrict__ Wk, const float* __restrict__ bk,
    const float* __restrict__ Wv, const float* __restrict__ bv,
    const float* __restrict__ Ws, const float* __restrict__ bs,
    float* __restrict__ out)
{
    __shared__ float xT[D][TNODE];     // 32KB, transposed x tile
    const int tid = threadIdx.x;
    const int n0  = blockIdx.x * TNODE;

    // stage x tile transposed; zero-pad invalid nodes
    for (int i = tid; i < 32 * TNODE; i += 256) {
        const int q = i >> 6, e = i & 63;
        float4 m = make_float4(0, 0, 0, 0);
        if (n0 + e < NN) m = __ldg((const float4*)(x + (size_t)(n0 + e) * D) + q);
        xT[4 * q + 0][e] = m.x; xT[4 * q + 1][e] = m.y;
        xT[4 * q + 2][e] = m.z; xT[4 * q + 3][e] = m.w;
    }
    __syncthreads();

    const int lane = tid & 31, w = tid >> 5;
    const float* Wlist[4] = {Wq, Wk, Wv, Ws};
    const float* blist[4] = {bq, bk, bv, bs};
    float*       dlist[4] = {g_q, g_k, g_v, out};

    #pragma unroll
    for (int m = 0; m < 4; m++) {
        const float4* W4 = (const float4*)Wlist[m];
        unsigned long long acc[4][4];
        #pragma unroll
        for (int i = 0; i < 4; i++)
            #pragma unroll
            for (int j = 0; j < 4; j++) acc[i][j] = 0ull;

        #pragma unroll 4
        for (int k = 0; k < D; k++) {
            const double2* ap = (const double2*)(&xT[k][w * 8]);
            double2 p0 = ap[0], p1 = ap[1];
            unsigned long long a0 = __double_as_longlong(p0.x);
            unsigned long long a1 = __double_as_longlong(p0.y);
            unsigned long long a2 = __double_as_longlong(p1.x);
            unsigned long long a3 = __double_as_longlong(p1.y);
            const float4 wv = __ldg(W4 + k * 32 + lane);
            unsigned long long w0 = dup2(wv.x), w1 = dup2(wv.y),
                               w2 = dup2(wv.z), w3 = dup2(wv.w);
            fma2(acc[0][0], a0, w0); fma2(acc[0][1], a0, w1);
            fma2(acc[0][2], a0, w2); fma2(acc[0][3], a0, w3);
            fma2(acc[1][0], a1, w0); fma2(acc[1][1], a1, w1);
            fma2(acc[1][2], a1, w2); fma2(acc[1][3], a1, w3);
            fma2(acc[2][0], a2, w0); fma2(acc[2][1], a2, w1);
            fma2(acc[2][2], a2, w2); fma2(acc[2][3], a2, w3);
            fma2(acc[3][0], a3, w0); fma2(acc[3][1], a3, w1);
            fma2(acc[3][2], a3, w2); fma2(acc[3][3], a3, w3);
        }

        const float4 bb = __ldg((const float4*)blist[m] + lane);
        float* dst = dlist[m];
        #pragma unroll
        for (int i = 0; i < 4; i++) {
            const int nA = n0 + w * 8 + i * 2;
            if (nA < NN) {
                float4 o = make_float4(lo32(acc[i][0]) + bb.x, lo32(acc[i][1]) + bb.y,
                                       lo32(acc[i][2]) + bb.z, lo32(acc[i][3]) + bb.w);
                *(float4*)(dst + (size_t)nA * D + lane * 4) = o;
            }
            if (nA + 1 < NN) {
                float4 o = make_float4(hi32(acc[i][0]) + bb.x, hi32(acc[i][1]) + bb.y,
                                       hi32(acc[i][2]) + bb.z, hi32(acc[i][3]) + bb.w);
                *(float4*)(dst + (size_t)(nA + 1) * D + lane * 4) = o;
            }
        }
    }
}

// ---- edge: attr build + attr@We GEMM + attention + atomic scatter ----
__global__ __launch_bounds__(256) void edge_kernel(
    const void*  __restrict__ ei_raw,
    const float* __restrict__ last_update,
    const float* __restrict__ t,
    const float* __restrict__ msg,
    const float* __restrict__ time_w,
    const float* __restrict__ time_b,
    const float* __restrict__ We)
{
    __shared__ float attrT[EDIM][TE];   // 40KB, transposed edge_attr tile
    __shared__ int   s_src[TE], s_dst[TE];
    __shared__ float s_rel[TE];
    const int tid = threadIdx.x;
    const int e0  = blockIdx.x * TE;

    if (tid < TE) {
        const int eg = e0 + tid;
        int src = 0, dst = 0; float rel = 0.f;
        if (eg < NE) {
            if (g_idx64) {
                const long long* p = (const long long*)ei_raw;
                src = (int)__ldg(p + eg); dst = (int)__ldg(p + NE + eg);
            } else {
                const int* p = (const int*)ei_raw;
                src = __ldg(p + eg); dst = __ldg(p + NE + eg);
            }
            rel = __ldg(last_update + src) - __ldg(t + eg);
        }
        s_src[tid] = src; s_dst[tid] = dst; s_rel[tid] = rel;
    }
    __syncthreads();

    // time-encoding rows [0,32)
    for (int i = tid; i < TDIM * TE; i += 256) {
        const int k = i >> 6, e = i & 63;
        attrT[k][e] = (e0 + e < NE)
            ? cosf(s_rel[e] * __ldg(time_w + k) + __ldg(time_b + k)) : 0.f;
    }
    // msg rows [32,160)
    for (int i = tid; i < 32 * TE; i += 256) {
        const int q = i >> 6, e = i & 63;
        float4 m = make_float4(0, 0, 0, 0);
        if (e0 + e < NE) m = __ldg((const float4*)(msg + (size_t)(e0 + e) * D) + q);
        attrT[TDIM + 4 * q + 0][e] = m.x; attrT[TDIM + 4 * q + 1][e] = m.y;
        attrT[TDIM + 4 * q + 2][e] = m.z; attrT[TDIM + 4 * q + 3][e] = m.w;
    }
    __syncthreads();

    const int lane = tid & 31, w = tid >> 5;
    const float4* We4 = (const float4*)We;

    unsigned long long acc[4][4];
    #pragma unroll
    for (int i = 0; i < 4; i++)
        #pragma unroll
        for (int j = 0; j < 4; j++) acc[i][j] = 0ull;

    #pragma unroll 4
    for (int k = 0; k < EDIM; k++) {
        const double2* ap = (const double2*)(&attrT[k][w * 8]);
        double2 p0 = ap[0], p1 = ap[1];
        unsigned long long a0 = __double_as_longlong(p0.x);
        unsigned long long a1 = __double_as_longlong(p0.y);
        unsigned long long a2 = __double_as_longlong(p1.x);
        unsigned long long a3 = __double_as_longlong(p1.y);
        const float4 wv = __ldg(We4 + k * 32 + lane);
        unsigned long long w0 = dup2(wv.x), w1 = dup2(wv.y),
                           w2 = dup2(wv.z), w3 = dup2(wv.w);
        fma2(acc[0][0], a0, w0); fma2(acc[0][1], a0, w1);
        fma2(acc[0][2], a0, w2); fma2(acc[0][3], a0, w3);
        fma2(acc[1][0], a1, w0); fma2(acc[1][1], a1, w1);
        fma2(acc[1][2], a1, w2); fma2(acc[1][3], a1, w3);
        fma2(acc[2][0], a2, w0); fma2(acc[2][1], a2, w1);
        fma2(acc[2][2], a2, w2); fma2(acc[2][3], a2, w3);
        fma2(acc[3][0], a3, w0); fma2(acc[3][1], a3, w1);
        fma2(acc[3][2], a3, w2); fma2(acc[3][3], a3, w3);
    }

    // epilogue: per warp, 8 edges; lane owns cols [4*lane, 4*lane+4)
    const int col = lane * 4;
    #pragma unroll
    for (int i = 0; i < 4; i++) {
        #pragma unroll
        for (int half = 0; half < 2; half++) {
            const int eL = w * 8 + i * 2 + half;
            const int eg = e0 + eL;
            const bool valid = eg < NE;
            const int src = s_src[eL], dst = s_dst[eL];
            float e0v = half ? hi32(acc[i][0]) : lo32(acc[i][0]);
            float e1v = half ? hi32(acc[i][1]) : lo32(acc[i][1]);
            float e2v = half ? hi32(acc[i][2]) : lo32(acc[i][2]);
            float e3v = half ? hi32(acc[i][3]) : lo32(acc[i][3]);

            const float4 qi = *(const float4*)(g_q + (size_t)dst * D + col);
            float4 kj = *(const float4*)(g_k + (size_t)src * D + col);
            float4 vj = *(const float4*)(g_v + (size_t)src * D + col);
            kj.x += e0v; kj.y += e1v; kj.z += e2v; kj.w += e3v;
            vj.x += e0v; vj.y += e1v; vj.z += e2v; vj.w += e3v;

            float p = qi.x * kj.x + qi.y * kj.y + qi.z * kj.z + qi.w * kj.w;
            p += __shfl_xor_sync(0xffffffffu, p, 1);
            p += __shfl_xor_sync(0xffffffffu, p, 2);
            p += __shfl_xor_sync(0xffffffffu, p, 4);
            p += __shfl_xor_sync(0xffffffffu, p, 8);
            const float ex = expf(p * 0.125f);   // 1/sqrt(64); exact softmax w/o max-sub

            if (valid) {
                red_v4(g_agg + (size_t)dst * D + col,
                       ex * vj.x, ex * vj.y, ex * vj.z, ex * vj.w);
                if ((lane & 15) == 0)
                    red_1(&g_sum[dst * 2 + (lane >> 4)], ex);
            }
        }
    }
}

__global__ void finalize_kernel(float* __restrict__ out) {
    int idx = blockIdx.x * blockDim.x + threadIdx.x;   // one float4 per thread
    if (idx >= NN * 32) return;
    const int n = idx >> 5;
    const int h = (idx & 31) >> 4;
    const float inv = 1.0f / (g_sum[n * 2 + h] + 1e-16f);
    float4 a = ((const float4*)g_agg)[idx];
    float4 o = ((float4*)out)[idx];
    o.x += a.x * inv; o.y += a.y * inv; o.z += a.z * inv; o.w += a.w * inv;
    ((float4*)out)[idx] = o;
}

extern "C" void kernel_launch(void* const* d_in, const int* in_sizes, int n_in,
                              void* d_out, int out_size) {
    const float* x           = (const float*)d_in[0];
    const float* last_update = (const float*)d_in[1];
    const void*  ei          = d_in[2];
    const float* t           = (const float*)d_in[3];
    const float* msg         = (const float*)d_in[4];
    const float* time_w      = (const float*)d_in[5];
    const float* time_b      = (const float*)d_in[6];
    const float* Wq          = (const float*)d_in[7];
    const float* bq          = (const float*)d_in[8];
    const float* Wk          = (const float*)d_in[9];
    const float* bk          = (const float*)d_in[10];
    const float* Wv          = (const float*)d_in[11];
    const float* bv          = (const float*)d_in[12];
    const float* We          = (const float*)d_in[13];
    const float* Ws          = (const float*)d_in[14];
    const float* bs          = (const float*)d_in[15];
    float* out = (float*)d_out;

    detect_kernel<<<1, 32>>>((const long long*)ei);
    zero_kernel<<<(NN * D + 255) / 256, 256>>>();
    proj_kernel<<<(NN + TNODE - 1) / TNODE, 256>>>(x, Wq, bq, Wk, bk, Wv, bv, Ws, bs, out);
    edge_kernel<<<(NE + TE - 1) / TE, 256>>>(ei, last_update, t, msg, time_w, time_b, We);
    finalize_kernel<<<(NN * 32 + 255) / 256, 256>>>(out);
}